// round 6
// baseline (speedup 1.0000x reference)
#include <cuda_runtime.h>
#include <cuda_bf16.h>
#include <math_constants.h>
#include <cstdint>

#define B_ 4
#define C_ 128
#define N_ 4096
#define TQ 128           // queries per CTA
#define TK 64            // keys per iteration
#define NT (N_ / TK)     // 64 iterations

// bf16 hi/lo scratch, all token-major [B][N][C]
__device__ __nv_bfloat16 g_qh[B_*N_*C_], g_ql[B_*N_*C_];
__device__ __nv_bfloat16 g_kh[B_*N_*C_], g_kl[B_*N_*C_];
__device__ __nv_bfloat16 g_vh[B_*N_*C_], g_vl[B_*N_*C_];

// ---------------- helpers ----------------
__device__ __forceinline__ uint32_t smem_u32(const void* p) {
    uint32_t a;
    asm("{ .reg .u64 t; cvta.to.shared.u64 t, %1; cvt.u32.u64 %0, t; }"
        : "=r"(a) : "l"(p));
    return a;
}
__device__ __forceinline__ void cpa16(uint32_t dst, const void* src) {
    asm volatile("cp.async.cg.shared.global [%0], [%1], 16;" :: "r"(dst), "l"(src));
}
__device__ __forceinline__ void cpa_commit() {
    asm volatile("cp.async.commit_group;" ::: "memory");
}
template<int NG> __device__ __forceinline__ void cpa_wait() {
    asm volatile("cp.async.wait_group %0;" :: "n"(NG) : "memory");
}
__device__ __forceinline__ void ldsm4(uint32_t* r, uint32_t a) {
    asm volatile("ldmatrix.sync.aligned.m8n8.x4.shared.b16 {%0,%1,%2,%3}, [%4];"
                 : "=r"(r[0]), "=r"(r[1]), "=r"(r[2]), "=r"(r[3]) : "r"(a));
}
__device__ __forceinline__ void ldsm4t(uint32_t* r, uint32_t a) {
    asm volatile("ldmatrix.sync.aligned.m8n8.x4.trans.shared.b16 {%0,%1,%2,%3}, [%4];"
                 : "=r"(r[0]), "=r"(r[1]), "=r"(r[2]), "=r"(r[3]) : "r"(a));
}
__device__ __forceinline__ void mma16816(float* d, const uint32_t* a,
                                         const uint32_t* b) {
    asm volatile(
        "mma.sync.aligned.m16n8k16.row.col.f32.bf16.bf16.f32 "
        "{%0,%1,%2,%3}, {%4,%5,%6,%7}, {%8,%9}, {%0,%1,%2,%3};"
        : "+f"(d[0]), "+f"(d[1]), "+f"(d[2]), "+f"(d[3])
        : "r"(a[0]), "r"(a[1]), "r"(a[2]), "r"(a[3]), "r"(b[0]), "r"(b[1]));
}
__device__ __forceinline__ uint32_t pack_bf16(float lo, float hi) {
    uint32_t ul = (uint32_t)__bfloat16_as_ushort(__float2bfloat16_rn(lo));
    uint32_t uh = (uint32_t)__bfloat16_as_ushort(__float2bfloat16_rn(hi));
    return (uh << 16) | ul;
}
// smem row = 256 B (128 bf16). 16B-chunk XOR swizzle: conflict-free ldmatrix.
__device__ __forceinline__ uint32_t swadr(uint32_t base, int row, int chunk) {
    return base + row * 256 + ((chunk ^ (row & 7)) << 4);
}

// SMEM layout (bytes):
// QH 0..32K, QL 32K..64K
// stage s (s=0,1) at 64K + s*64K: KH +0, KL +16K, VH +32K, VL +48K
// RED scratch (m0 / l exchange): 196608..197632
// epilogue: O-partial [128][132] fp32 at base (Q + stage0 dead)
#define OFF_Q    0
#define OFF_KV   65536
#define STAGE_SZ 65536
#define OFF_RED  196608
#define SMEM_ATTN 197632

// ---------------------------------------------------------------------------
// QKV projection (fp32 SIMT GEMM) -> bf16 hi/lo token-major [B][N][C]
// ---------------------------------------------------------------------------
__global__ __launch_bounds__(256) void qkv_kernel(
    const float* __restrict__ x,
    const float* __restrict__ wq, const float* __restrict__ bq,
    const float* __restrict__ wk, const float* __restrict__ bk,
    const float* __restrict__ wv, const float* __restrict__ bv)
{
    extern __shared__ float sm[];
    float* Xs = sm;          // 128*64
    float* Ws = sm + 8192;   // 64*128

    const int tid = threadIdx.x;
    const int tx = tid & 15, ty = tid >> 4;
    const int ntile = blockIdx.x, otile = blockIdx.y, b = blockIdx.z;

    const float* w; const float* bias;
    __nv_bfloat16 *oh, *ol;
    if (otile < 2)      { w = wq; bias = bq; oh = g_qh; ol = g_ql; }
    else if (otile < 4) { w = wk; bias = bk; oh = g_kh; ol = g_kl; }
    else                { w = wv; bias = bv; oh = g_vh; ol = g_vl; }
    const int orow0 = (otile & 1) * 64;
    const int n0 = ntile * 64;

    #pragma unroll
    for (int p = 0; p < 32; p++) {
        int idx = tid + p * 256;
        Ws[idx] = w[(orow0 + (idx >> 7)) * C_ + (idx & 127)];
    }
    #pragma unroll
    for (int p = 0; p < 32; p++) {
        int idx = tid + p * 256;
        Xs[idx] = x[(b * C_ + (idx >> 6)) * N_ + n0 + (idx & 63)];
    }
    __syncthreads();

    float acc[4][4];
    #pragma unroll
    for (int i = 0; i < 4; i++)
        #pragma unroll
        for (int j = 0; j < 4; j++) acc[i][j] = 0.f;

    #pragma unroll 8
    for (int c = 0; c < 128; c++) {
        float4 xf = *(const float4*)&Xs[c * 64 + tx * 4];
        #pragma unroll
        for (int i = 0; i < 4; i++) {
            float wf = Ws[(ty * 4 + i) * 128 + c];
            acc[i][0] += wf * xf.x; acc[i][1] += wf * xf.y;
            acc[i][2] += wf * xf.z; acc[i][3] += wf * xf.w;
        }
    }

    float bb[4];
    #pragma unroll
    for (int i = 0; i < 4; i++) bb[i] = bias[orow0 + ty * 4 + i];

    #pragma unroll
    for (int j = 0; j < 4; j++) {
        int n = n0 + tx * 4 + j;
        __nv_bfloat16 h[4], l[4];
        #pragma unroll
        for (int i = 0; i < 4; i++) {
            float v = acc[i][j] + bb[i];
            h[i] = __float2bfloat16_rn(v);
            l[i] = __float2bfloat16_rn(v - __bfloat162float(h[i]));
        }
        size_t base = (size_t)(b * N_ + n) * C_ + orow0 + ty * 4;
        *(uint2*)&oh[base] = *(uint2*)h;
        *(uint2*)&ol[base] = *(uint2*)l;
    }
}

// ---------------------------------------------------------------------------
// mma.sync flash attention, bf16x3, 16 warps: warp (qt, kh) handles
// query rows [qt*16, qt*16+16) x key half kh of every 64-key tile.
// Grid (N/128, B), 512 threads.
// ---------------------------------------------------------------------------
__global__ __launch_bounds__(512, 1) void attn_kernel(float* __restrict__ out)
{
    extern __shared__ char smem[];
    const uint32_t sb = smem_u32(smem);
    const int tid = threadIdx.x;
    const int w = tid >> 5, lane = tid & 31;
    const int qt = w >> 1, kh = w & 1;
    const int b = blockIdx.y;
    const int q0 = blockIdx.x * TQ;

    const uint32_t sbQH = sb + OFF_Q;
    float* red = (float*)(smem + OFF_RED);   // [128][2]

    // ---- prologue: Q (hi/lo) + stage 0 ----
    #pragma unroll
    for (int i = 0; i < 4; i++) {
        int idx = tid + i * 512;              // 2048 chunks
        int row = idx >> 4, ch = idx & 15;
        uint32_t dst = swadr(sbQH, row, ch);
        size_t g = ((size_t)(b * N_ + q0 + row) * C_) * 2 + ch * 16;
        cpa16(dst, (const char*)g_qh + g);
        cpa16(dst + 32768, (const char*)g_ql + g);
    }
    {
        const uint32_t st = sb + OFF_KV;
        #pragma unroll
        for (int i = 0; i < 2; i++) {
            int idx = tid + i * 512;          // 1024 chunks
            int row = idx >> 4, ch = idx & 15;
            uint32_t dst = swadr(st, row, ch);
            size_t g = ((size_t)(b * N_ + row) * C_) * 2 + ch * 16;
            cpa16(dst,         (const char*)g_kh + g);
            cpa16(dst + 16384, (const char*)g_kl + g);
            cpa16(dst + 32768, (const char*)g_vh + g);
            cpa16(dst + 49152, (const char*)g_vl + g);
        }
    }
    cpa_commit();

    float oacc[16][4];
    #pragma unroll
    for (int n = 0; n < 16; n++)
        #pragma unroll
        for (int c = 0; c < 4; c++) oacc[n][c] = 0.f;
    float m0r0 = 0.f, m0r1 = 0.f, lr0 = 0.f, lr1 = 0.f;
    const int row0 = qt * 16 + (lane >> 2);   // accum rows (c0,c1)
    const int row1 = row0 + 8;                // accum rows (c2,c3)

    #pragma unroll 1
    for (int t = 0; t < NT; t++) {
        const uint32_t st = sb + OFF_KV + (t & 1) * STAGE_SZ;

        if (t + 1 < NT) {
            const uint32_t nst = sb + OFF_KV + ((t + 1) & 1) * STAGE_SZ;
            const int k0 = (t + 1) * TK;
            #pragma unroll
            for (int i = 0; i < 2; i++) {
                int idx = tid + i * 512;
                int row = idx >> 4, ch = idx & 15;
                uint32_t dst = swadr(nst, row, ch);
                size_t g = ((size_t)(b * N_ + k0 + row) * C_) * 2 + ch * 16;
                cpa16(dst,         (const char*)g_kh + g);
                cpa16(dst + 16384, (const char*)g_kl + g);
                cpa16(dst + 32768, (const char*)g_vh + g);
                cpa16(dst + 49152, (const char*)g_vl + g);
            }
            cpa_commit();
            cpa_wait<1>();
        } else {
            cpa_wait<0>();
        }
        __syncthreads();

        // ---- S = Q Kt^T, bf16x3, per-warp 16 x 32 (key half kh) ----
        float sacc[4][4];
        #pragma unroll
        for (int n = 0; n < 4; n++)
            #pragma unroll
            for (int c = 0; c < 4; c++) sacc[n][c] = 0.f;

        #pragma unroll
        for (int ks = 0; ks < 8; ks++) {
            uint32_t qh4[4], ql4[4];
            int qrow = qt * 16 + (lane & 15);
            int qch = ks * 2 + (lane >> 4);
            uint32_t qa = swadr(sbQH, qrow, qch);
            ldsm4(qh4, qa);
            ldsm4(ql4, qa + 32768);
            #pragma unroll
            for (int np = 0; np < 2; np++) {
                uint32_t khp[4], klp[4];
                int krow = kh * 32 + (2 * np + (lane >> 4)) * 8 + (lane & 7);
                int kch = ks * 2 + ((lane >> 3) & 1);
                uint32_t ka = swadr(st, krow, kch);
                ldsm4(khp, ka);
                ldsm4(klp, ka + 16384);
                mma16816(sacc[2*np],   qh4, khp);
                mma16816(sacc[2*np+1], qh4, khp + 2);
                mma16816(sacc[2*np],   qh4, klp);
                mma16816(sacc[2*np+1], qh4, klp + 2);
                mma16816(sacc[2*np],   ql4, khp);
                mma16816(sacc[2*np+1], ql4, khp + 2);
            }
        }

        // ---- fixed m0 from tile 0 (shared across the warp pair) ----
        if (t == 0) {
            float mx0 = -CUDART_INF_F, mx1 = -CUDART_INF_F;
            #pragma unroll
            for (int n = 0; n < 4; n++) {
                mx0 = fmaxf(mx0, fmaxf(sacc[n][0], sacc[n][1]));
                mx1 = fmaxf(mx1, fmaxf(sacc[n][2], sacc[n][3]));
            }
            #pragma unroll
            for (int off = 1; off <= 2; off <<= 1) {
                mx0 = fmaxf(mx0, __shfl_xor_sync(0xffffffffu, mx0, off));
                mx1 = fmaxf(mx1, __shfl_xor_sync(0xffffffffu, mx1, off));
            }
            if ((lane & 3) == 0) {
                red[row0 * 2 + kh] = mx0;
                red[row1 * 2 + kh] = mx1;
            }
            __syncthreads();
            m0r0 = fmaxf(red[row0 * 2], red[row0 * 2 + 1]);
            m0r1 = fmaxf(red[row1 * 2], red[row1 * 2 + 1]);
        }

        // ---- fused softmax + PV per 16-key chunk (2 chunks) ----
        const uint32_t vst = st + 32768;
        #pragma unroll
        for (int kk = 0; kk < 2; kk++) {
            uint32_t ph[4], pl[4];
            #pragma unroll
            for (int half = 0; half < 2; half++) {
                int n = 2 * kk + half;
                float p0 = __expf(sacc[n][0] - m0r0);
                float p1 = __expf(sacc[n][1] - m0r0);
                float p2 = __expf(sacc[n][2] - m0r1);
                float p3 = __expf(sacc[n][3] - m0r1);
                lr0 += p0 + p1; lr1 += p2 + p3;
                uint32_t h01 = pack_bf16(p0, p1);
                uint32_t h23 = pack_bf16(p2, p3);
                float h0 = __bfloat162float(__ushort_as_bfloat16((unsigned short)(h01 & 0xffff)));
                float h1 = __bfloat162float(__ushort_as_bfloat16((unsigned short)(h01 >> 16)));
                float h2 = __bfloat162float(__ushort_as_bfloat16((unsigned short)(h23 & 0xffff)));
                float h3 = __bfloat162float(__ushort_as_bfloat16((unsigned short)(h23 >> 16)));
                ph[half * 2]     = h01;
                ph[half * 2 + 1] = h23;
                pl[half * 2]     = pack_bf16(p0 - h0, p1 - h1);
                pl[half * 2 + 1] = pack_bf16(p2 - h2, p3 - h3);
            }
            #pragma unroll
            for (int np = 0; np < 8; np++) {
                uint32_t vh[4], vl[4];
                uint32_t va = swadr(vst, kh * 32 + kk * 16 + (lane & 15),
                                    2 * np + (lane >> 4));
                ldsm4t(vh, va);
                ldsm4t(vl, va + 16384);
                mma16816(oacc[2*np],   ph, vh);
                mma16816(oacc[2*np+1], ph, vh + 2);
                mma16816(oacc[2*np],   ph, vl);
                mma16816(oacc[2*np+1], ph, vl + 2);
                mma16816(oacc[2*np],   pl, vh);
                mma16816(oacc[2*np+1], pl, vh + 2);
            }
        }
        __syncthreads();
    }

    // ---- epilogue: cross-pair O and l reduction through smem ----
    #pragma unroll
    for (int off = 1; off <= 2; off <<= 1) {
        lr0 += __shfl_xor_sync(0xffffffffu, lr0, off);
        lr1 += __shfl_xor_sync(0xffffffffu, lr1, off);
    }
    if ((lane & 3) == 0) {
        red[row0 * 2 + kh] = lr0;
        red[row1 * 2 + kh] = lr1;
    }
    float* Op = (float*)smem;                 // [128][132] fp32 (Q/stage0 dead)
    __syncthreads();
    if (kh == 1) {
        #pragma unroll
        for (int nn = 0; nn < 16; nn++) {
            int ch = nn * 8 + (lane & 3) * 2;
            Op[row0 * 132 + ch]     = oacc[nn][0];
            Op[row0 * 132 + ch + 1] = oacc[nn][1];
            Op[row1 * 132 + ch]     = oacc[nn][2];
            Op[row1 * 132 + ch + 1] = oacc[nn][3];
        }
    }
    __syncthreads();
    if (kh == 0) {
        float inv0 = 1.f / (red[row0 * 2] + red[row0 * 2 + 1]);
        float inv1 = 1.f / (red[row1 * 2] + red[row1 * 2 + 1]);
        int qa0 = q0 + row0, qa1 = q0 + row1;
        #pragma unroll
        for (int nn = 0; nn < 16; nn++) {
            int ch = nn * 8 + (lane & 3) * 2;
            out[((size_t)b * C_ + ch) * N_ + qa0] =
                (oacc[nn][0] + Op[row0 * 132 + ch]) * inv0;
            out[((size_t)b * C_ + ch + 1) * N_ + qa0] =
                (oacc[nn][1] + Op[row0 * 132 + ch + 1]) * inv0;
            out[((size_t)b * C_ + ch) * N_ + qa1] =
                (oacc[nn][2] + Op[row1 * 132 + ch]) * inv1;
            out[((size_t)b * C_ + ch + 1) * N_ + qa1] =
                (oacc[nn][3] + Op[row1 * 132 + ch + 1]) * inv1;
        }
    }
}

// ---------------------------------------------------------------------------
extern "C" void kernel_launch(void* const* d_in, const int* in_sizes, int n_in,
                              void* d_out, int out_size)
{
    const float* x  = (const float*)d_in[0];
    const float* wq = (const float*)d_in[1];
    const float* bq = (const float*)d_in[2];
    const float* wk = (const float*)d_in[3];
    const float* bk = (const float*)d_in[4];
    const float* wv = (const float*)d_in[5];
    const float* bv = (const float*)d_in[6];
    float* out = (float*)d_out;

    cudaFuncSetAttribute(qkv_kernel,
                         cudaFuncAttributeMaxDynamicSharedMemorySize, 65536);
    cudaFuncSetAttribute(attn_kernel,
                         cudaFuncAttributeMaxDynamicSharedMemorySize, SMEM_ATTN);

    qkv_kernel<<<dim3(64, 6, 4), 256, 65536>>>(x, wq, bq, wk, bk, wv, bv);
    attn_kernel<<<dim3(N_ / TQ, B_), 512, SMEM_ATTN>>>(out);
}

// round 7
// speedup vs baseline: 1.0597x; 1.0597x over previous
#include <cuda_runtime.h>
#include <cuda_bf16.h>
#include <math_constants.h>
#include <cstdint>

#define B_ 4
#define C_ 128
#define N_ 4096
#define TQ 64            // queries per CTA
#define TK 32            // keys per iteration
#define NT (N_ / TK)     // 128 iterations

// bf16 hi/lo scratch, all token-major [B][N][C]
__device__ __nv_bfloat16 g_qh[B_*N_*C_], g_ql[B_*N_*C_];
__device__ __nv_bfloat16 g_kh[B_*N_*C_], g_kl[B_*N_*C_];
__device__ __nv_bfloat16 g_vh[B_*N_*C_], g_vl[B_*N_*C_];

// ---------------- helpers ----------------
__device__ __forceinline__ uint32_t smem_u32(const void* p) {
    uint32_t a;
    asm("{ .reg .u64 t; cvta.to.shared.u64 t, %1; cvt.u32.u64 %0, t; }"
        : "=r"(a) : "l"(p));
    return a;
}
__device__ __forceinline__ void cpa16(uint32_t dst, const void* src) {
    asm volatile("cp.async.cg.shared.global [%0], [%1], 16;" :: "r"(dst), "l"(src));
}
__device__ __forceinline__ void cpa_commit() {
    asm volatile("cp.async.commit_group;" ::: "memory");
}
template<int NG> __device__ __forceinline__ void cpa_wait() {
    asm volatile("cp.async.wait_group %0;" :: "n"(NG) : "memory");
}
__device__ __forceinline__ void ldsm4(uint32_t* r, uint32_t a) {
    asm volatile("ldmatrix.sync.aligned.m8n8.x4.shared.b16 {%0,%1,%2,%3}, [%4];"
                 : "=r"(r[0]), "=r"(r[1]), "=r"(r[2]), "=r"(r[3]) : "r"(a));
}
__device__ __forceinline__ void ldsm4t(uint32_t* r, uint32_t a) {
    asm volatile("ldmatrix.sync.aligned.m8n8.x4.trans.shared.b16 {%0,%1,%2,%3}, [%4];"
                 : "=r"(r[0]), "=r"(r[1]), "=r"(r[2]), "=r"(r[3]) : "r"(a));
}
__device__ __forceinline__ void mma16816(float* d, const uint32_t* a,
                                         const uint32_t* b) {
    asm volatile(
        "mma.sync.aligned.m16n8k16.row.col.f32.bf16.bf16.f32 "
        "{%0,%1,%2,%3}, {%4,%5,%6,%7}, {%8,%9}, {%0,%1,%2,%3};"
        : "+f"(d[0]), "+f"(d[1]), "+f"(d[2]), "+f"(d[3])
        : "r"(a[0]), "r"(a[1]), "r"(a[2]), "r"(a[3]), "r"(b[0]), "r"(b[1]));
}
__device__ __forceinline__ uint32_t pack_bf16(float lo, float hi) {
    uint32_t ul = (uint32_t)__bfloat16_as_ushort(__float2bfloat16_rn(lo));
    uint32_t uh = (uint32_t)__bfloat16_as_ushort(__float2bfloat16_rn(hi));
    return (uh << 16) | ul;
}
// smem row = 256 B (128 bf16). 16B-chunk XOR swizzle: conflict-free ldmatrix.
__device__ __forceinline__ uint32_t swadr(uint32_t base, int row, int chunk) {
    return base + row * 256 + ((chunk ^ (row & 7)) << 4);
}

// SMEM layout (bytes): QH 0..16K, QL 16K..32K
// stage s at 32K + s*32K: KH +0, KL +8K, VH +16K, VL +24K
#define OFF_Q    0
#define OFF_KV   32768
#define STAGE_SZ 32768
#define SMEM_ATTN 98304

// ---------------------------------------------------------------------------
// QKV projection (fp32 SIMT GEMM) -> bf16 hi/lo token-major [B][N][C]
// ---------------------------------------------------------------------------
__global__ __launch_bounds__(256) void qkv_kernel(
    const float* __restrict__ x,
    const float* __restrict__ wq, const float* __restrict__ bq,
    const float* __restrict__ wk, const float* __restrict__ bk,
    const float* __restrict__ wv, const float* __restrict__ bv)
{
    extern __shared__ float sm[];
    float* Xs = sm;          // 128*64
    float* Ws = sm + 8192;   // 64*128

    const int tid = threadIdx.x;
    const int tx = tid & 15, ty = tid >> 4;
    const int ntile = blockIdx.x, otile = blockIdx.y, b = blockIdx.z;

    const float* w; const float* bias;
    __nv_bfloat16 *oh, *ol;
    if (otile < 2)      { w = wq; bias = bq; oh = g_qh; ol = g_ql; }
    else if (otile < 4) { w = wk; bias = bk; oh = g_kh; ol = g_kl; }
    else                { w = wv; bias = bv; oh = g_vh; ol = g_vl; }
    const int orow0 = (otile & 1) * 64;
    const int n0 = ntile * 64;

    #pragma unroll
    for (int p = 0; p < 32; p++) {
        int idx = tid + p * 256;
        Ws[idx] = w[(orow0 + (idx >> 7)) * C_ + (idx & 127)];
    }
    #pragma unroll
    for (int p = 0; p < 32; p++) {
        int idx = tid + p * 256;
        Xs[idx] = x[(b * C_ + (idx >> 6)) * N_ + n0 + (idx & 63)];
    }
    __syncthreads();

    float acc[4][4];
    #pragma unroll
    for (int i = 0; i < 4; i++)
        #pragma unroll
        for (int j = 0; j < 4; j++) acc[i][j] = 0.f;

    #pragma unroll 8
    for (int c = 0; c < 128; c++) {
        float4 xf = *(const float4*)&Xs[c * 64 + tx * 4];
        #pragma unroll
        for (int i = 0; i < 4; i++) {
            float wf = Ws[(ty * 4 + i) * 128 + c];
            acc[i][0] += wf * xf.x; acc[i][1] += wf * xf.y;
            acc[i][2] += wf * xf.z; acc[i][3] += wf * xf.w;
        }
    }

    float bb[4];
    #pragma unroll
    for (int i = 0; i < 4; i++) bb[i] = bias[orow0 + ty * 4 + i];

    #pragma unroll
    for (int j = 0; j < 4; j++) {
        int n = n0 + tx * 4 + j;
        __nv_bfloat16 h[4], l[4];
        #pragma unroll
        for (int i = 0; i < 4; i++) {
            float v = acc[i][j] + bb[i];
            h[i] = __float2bfloat16_rn(v);
            l[i] = __float2bfloat16_rn(v - __bfloat162float(h[i]));
        }
        size_t base = (size_t)(b * N_ + n) * C_ + orow0 + ty * 4;
        *(uint2*)&oh[base] = *(uint2*)h;
        *(uint2*)&ol[base] = *(uint2*)l;
    }
}

// ---------------------------------------------------------------------------
// mma.sync flash attention, bf16x3. 128 threads (4 warps), TQ=64, TK=32.
// 2 CTAs co-resident per SM decouple barrier phases.
// Q fragments register-resident (loaded once). Warp w owns rows [w*16,w*16+16).
// ---------------------------------------------------------------------------
__global__ __launch_bounds__(128, 2) void attn_kernel(float* __restrict__ out)
{
    extern __shared__ char smem[];
    const uint32_t sb = smem_u32(smem);
    const int tid = threadIdx.x;
    const int w = tid >> 5, lane = tid & 31;
    const int b = blockIdx.y;
    const int q0 = blockIdx.x * TQ;

    const uint32_t sbQH = sb + OFF_Q;

    // ---- prologue: Q (hi/lo) + stage 0 (group 0) ----
    #pragma unroll
    for (int i = 0; i < 8; i++) {
        int idx = tid + i * 128;              // 1024 chunks (64 rows x 16)
        int row = idx >> 4, ch = idx & 15;
        uint32_t dst = swadr(sbQH, row, ch);
        size_t g = ((size_t)(b * N_ + q0 + row) * C_) * 2 + ch * 16;
        cpa16(dst, (const char*)g_qh + g);
        cpa16(dst + 16384, (const char*)g_ql + g);
    }
    {
        const uint32_t st = sb + OFF_KV;
        #pragma unroll
        for (int i = 0; i < 4; i++) {
            int idx = tid + i * 128;          // 512 chunks (32 rows x 16)
            int row = idx >> 4, ch = idx & 15;
            uint32_t dst = swadr(st, row, ch);
            size_t g = ((size_t)(b * N_ + row) * C_) * 2 + ch * 16;
            cpa16(dst,         (const char*)g_kh + g);
            cpa16(dst + 8192,  (const char*)g_kl + g);
            cpa16(dst + 16384, (const char*)g_vh + g);
            cpa16(dst + 24576, (const char*)g_vl + g);
        }
    }
    cpa_commit();

    float oacc[16][4];
    #pragma unroll
    for (int n = 0; n < 16; n++)
        #pragma unroll
        for (int c = 0; c < 4; c++) oacc[n][c] = 0.f;
    float m0r0 = 0.f, m0r1 = 0.f, lr0 = 0.f, lr1 = 0.f;
    uint32_t qf[8][8];                        // register-resident Q frags

    #pragma unroll 1
    for (int t = 0; t < NT; t++) {
        const uint32_t st = sb + OFF_KV + (t & 1) * STAGE_SZ;

        if (t + 1 < NT) {
            const uint32_t nst = sb + OFF_KV + ((t + 1) & 1) * STAGE_SZ;
            const int k0 = (t + 1) * TK;
            #pragma unroll
            for (int i = 0; i < 4; i++) {
                int idx = tid + i * 128;
                int row = idx >> 4, ch = idx & 15;
                uint32_t dst = swadr(nst, row, ch);
                size_t g = ((size_t)(b * N_ + k0 + row) * C_) * 2 + ch * 16;
                cpa16(dst,         (const char*)g_kh + g);
                cpa16(dst + 8192,  (const char*)g_kl + g);
                cpa16(dst + 16384, (const char*)g_vh + g);
                cpa16(dst + 24576, (const char*)g_vl + g);
            }
            cpa_commit();
            cpa_wait<1>();
        } else {
            cpa_wait<0>();
        }
        __syncthreads();

        if (t == 0) {
            // one-time: extract Q fragments to registers
            #pragma unroll
            for (int ks = 0; ks < 8; ks++) {
                int qrow = w * 16 + (lane & 15);
                int qch = ks * 2 + (lane >> 4);
                uint32_t qa = swadr(sbQH, qrow, qch);
                ldsm4(&qf[ks][0], qa);
                ldsm4(&qf[ks][4], qa + 16384);
            }
        }

        // ---- S = Q Kt^T, bf16x3, per-warp 16 x 32 ----
        float sacc[4][4];
        #pragma unroll
        for (int n = 0; n < 4; n++)
            #pragma unroll
            for (int c = 0; c < 4; c++) sacc[n][c] = 0.f;

        #pragma unroll
        for (int ks = 0; ks < 8; ks++) {
            #pragma unroll
            for (int np = 0; np < 2; np++) {
                uint32_t khp[4], klp[4];
                int krow = (2 * np + (lane >> 4)) * 8 + (lane & 7);
                int kch = ks * 2 + ((lane >> 3) & 1);
                uint32_t ka = swadr(st, krow, kch);
                ldsm4(khp, ka);
                ldsm4(klp, ka + 8192);
                mma16816(sacc[2*np],   &qf[ks][0], khp);
                mma16816(sacc[2*np+1], &qf[ks][0], khp + 2);
                mma16816(sacc[2*np],   &qf[ks][0], klp);
                mma16816(sacc[2*np+1], &qf[ks][0], klp + 2);
                mma16816(sacc[2*np],   &qf[ks][4], khp);
                mma16816(sacc[2*np+1], &qf[ks][4], khp + 2);
            }
        }

        // ---- fixed m0 from tile 0 (per-row via quad shuffle) ----
        if (t == 0) {
            float mx0 = -CUDART_INF_F, mx1 = -CUDART_INF_F;
            #pragma unroll
            for (int n = 0; n < 4; n++) {
                mx0 = fmaxf(mx0, fmaxf(sacc[n][0], sacc[n][1]));
                mx1 = fmaxf(mx1, fmaxf(sacc[n][2], sacc[n][3]));
            }
            #pragma unroll
            for (int off = 1; off <= 2; off <<= 1) {
                mx0 = fmaxf(mx0, __shfl_xor_sync(0xffffffffu, mx0, off));
                mx1 = fmaxf(mx1, __shfl_xor_sync(0xffffffffu, mx1, off));
            }
            m0r0 = mx0; m0r1 = mx1;
        }

        // ---- fused softmax + PV per 16-key chunk (2 chunks) ----
        const uint32_t vst = st + 16384;
        #pragma unroll
        for (int kk = 0; kk < 2; kk++) {
            uint32_t ph[4], pl[4];
            #pragma unroll
            for (int half = 0; half < 2; half++) {
                int n = 2 * kk + half;
                float p0 = __expf(sacc[n][0] - m0r0);
                float p1 = __expf(sacc[n][1] - m0r0);
                float p2 = __expf(sacc[n][2] - m0r1);
                float p3 = __expf(sacc[n][3] - m0r1);
                lr0 += p0 + p1; lr1 += p2 + p3;
                uint32_t h01 = pack_bf16(p0, p1);
                uint32_t h23 = pack_bf16(p2, p3);
                float h0 = __bfloat162float(__ushort_as_bfloat16((unsigned short)(h01 & 0xffff)));
                float h1 = __bfloat162float(__ushort_as_bfloat16((unsigned short)(h01 >> 16)));
                float h2 = __bfloat162float(__ushort_as_bfloat16((unsigned short)(h23 & 0xffff)));
                float h3 = __bfloat162float(__ushort_as_bfloat16((unsigned short)(h23 >> 16)));
                ph[half * 2]     = h01;
                ph[half * 2 + 1] = h23;
                pl[half * 2]     = pack_bf16(p0 - h0, p1 - h1);
                pl[half * 2 + 1] = pack_bf16(p2 - h2, p3 - h3);
            }
            #pragma unroll
            for (int np = 0; np < 8; np++) {
                uint32_t vh[4], vl[4];
                uint32_t va = swadr(vst, kk * 16 + (lane & 15), 2 * np + (lane >> 4));
                ldsm4t(vh, va);
                ldsm4t(vl, va + 8192);
                mma16816(oacc[2*np],   ph, vh);
                mma16816(oacc[2*np+1], ph, vh + 2);
                mma16816(oacc[2*np],   ph, vl);
                mma16816(oacc[2*np+1], ph, vl + 2);
                mma16816(oacc[2*np],   pl, vh);
                mma16816(oacc[2*np+1], pl, vh + 2);
            }
        }
        __syncthreads();
    }

    // ---- epilogue: reduce l across quad, normalize, store ----
    #pragma unroll
    for (int off = 1; off <= 2; off <<= 1) {
        lr0 += __shfl_xor_sync(0xffffffffu, lr0, off);
        lr1 += __shfl_xor_sync(0xffffffffu, lr1, off);
    }
    float inv0 = 1.f / lr0, inv1 = 1.f / lr1;
    int qa = q0 + w * 16 + (lane >> 2);
    #pragma unroll
    for (int nn = 0; nn < 16; nn++) {
        int ch = nn * 8 + (lane & 3) * 2;
        out[((size_t)b * C_ + ch) * N_ + qa]           = oacc[nn][0] * inv0;
        out[((size_t)b * C_ + ch + 1) * N_ + qa]       = oacc[nn][1] * inv0;
        out[((size_t)b * C_ + ch) * N_ + qa + 8]       = oacc[nn][2] * inv1;
        out[((size_t)b * C_ + ch + 1) * N_ + qa + 8]   = oacc[nn][3] * inv1;
    }
}

// ---------------------------------------------------------------------------
extern "C" void kernel_launch(void* const* d_in, const int* in_sizes, int n_in,
                              void* d_out, int out_size)
{
    const float* x  = (const float*)d_in[0];
    const float* wq = (const float*)d_in[1];
    const float* bq = (const float*)d_in[2];
    const float* wk = (const float*)d_in[3];
    const float* bk = (const float*)d_in[4];
    const float* wv = (const float*)d_in[5];
    const float* bv = (const float*)d_in[6];
    float* out = (float*)d_out;

    cudaFuncSetAttribute(qkv_kernel,
                         cudaFuncAttributeMaxDynamicSharedMemorySize, 65536);
    cudaFuncSetAttribute(attn_kernel,
                         cudaFuncAttributeMaxDynamicSharedMemorySize, SMEM_ATTN);

    qkv_kernel<<<dim3(64, 6, 4), 256, 65536>>>(x, wq, bq, wk, bk, wv, bv);
    attn_kernel<<<dim3(N_ / TQ, B_), 128, SMEM_ATTN>>>(out);
}